// round 7
// baseline (speedup 1.0000x reference)
#include <cuda_runtime.h>
#include <cuda_fp16.h>

// ODECell, two-phase d-split:
//   Phase 1 (2048 blocks): partial sums over half the d-range, BB=2 batches.
//   Phase 2 (combine): add halves, fs/fA finish + 6 Euler steps.
// f16x2 tanh front-end (1 MUFU per 2 dims), f32x2 packed accumulation.

#define UNITS  128
#define IDIM   128
#define DP     (IDIM / 2)    // 64 d-pairs
#define DSPLIT 2
#define DPH    (DP / DSPLIT) // 32 d-pairs per block
#define BATCH  2048
#define BB     2
#define OMEGA  0.1f
#define DT_U   (0.1f / 6.0f)

typedef unsigned int       u32;
typedef unsigned long long u64;

// Transposed packed weights [d_pair][u]: {sH2, cH2, AH0, AH1}
__device__ uint4  g_w[DP * UNITS];
__device__ float  g_baseA[UNITS];
// Partial sums: [half][batch][unit] = (sum t*AH, sum t)
__device__ float2 g_part[DSPLIT][BATCH * UNITS];

__device__ __forceinline__ u32 h2u(__half2 h) {
    u32 r; __builtin_memcpy(&r, &h, 4); return r;
}
__device__ __forceinline__ __half2 u2h(u32 u) {
    __half2 r; __builtin_memcpy(&r, &u, 4); return r;
}
__device__ __forceinline__ u32 tanh2u(u32 z) {
    u32 y; asm("tanh.approx.f16x2 %0, %1;" : "=r"(y) : "r"(z)); return y;
}
__device__ __forceinline__ u64 pack2(float lo, float hi) {
    u64 p;
    asm("mov.b64 %0, {%1, %2};" : "=l"(p)
        : "r"(__float_as_uint(lo)), "r"(__float_as_uint(hi)));
    return p;
}
__device__ __forceinline__ u64 fma2(u64 a, u64 b, u64 c) {
    u64 d; asm("fma.rn.f32x2 %0, %1, %2, %3;" : "=l"(d) : "l"(a), "l"(b), "l"(c));
    return d;
}
__device__ __forceinline__ u64 add2(u64 a, u64 b) {
    u64 d; asm("add.rn.f32x2 %0, %1, %2;" : "=l"(d) : "l"(a), "l"(b));
    return d;
}
__device__ __forceinline__ float2 unpack2(u64 p) {
    u32 lo, hi;
    asm("mov.b64 {%0, %1}, %2;" : "=r"(lo), "=r"(hi) : "l"(p));
    return make_float2(__uint_as_float(lo), __uint_as_float(hi));
}

// One block per unit u, 64 threads (one per d-pair): pack weights + reduce baseA.
__global__ void ode_prep_kernel(const float* __restrict__ A,
                                const float* __restrict__ sigma,
                                const float* __restrict__ mu) {
    const int u  = blockIdx.x;
    const int d2 = threadIdx.x;
    const int i  = u * IDIM + 2 * d2;

    float s0 = sigma[i],  s1 = sigma[i + 1];
    float m0 = mu[i],     m1 = mu[i + 1];
    float a0 = 0.5f * A[i], a1 = 0.5f * A[i + 1];

    __half2 sh2 = __halves2half2(__float2half_rn(0.5f * s0), __float2half_rn(0.5f * s1));
    __half2 ch2 = __halves2half2(__float2half_rn(-0.5f * s0 * m0),
                                 __float2half_rn(-0.5f * s1 * m1));

    uint4 w;
    w.x = h2u(sh2);
    w.y = h2u(ch2);
    w.z = __float_as_uint(a0);
    w.w = __float_as_uint(a1);
    g_w[d2 * UNITS + u] = w;

    __shared__ float red[2];
    float v = a0 + a1;
    #pragma unroll
    for (int off = 16; off > 0; off >>= 1)
        v += __shfl_down_sync(0xffffffffu, v, off);
    if ((d2 & 31) == 0) red[d2 >> 5] = v;
    __syncthreads();
    if (d2 == 0) g_baseA[u] = red[0] + red[1];
}

// Phase 1: blockIdx.x = batch_pair * DSPLIT + half.
__global__ __launch_bounds__(UNITS, 8)   // 64-reg budget, 8 blocks/SM
void ode_partial_kernel(const float* __restrict__ inputs) {
    const int u    = threadIdx.x;
    const int half = blockIdx.x & (DSPLIT - 1);
    const int b0   = (blockIdx.x / DSPLIT) * BB;
    const int dbase = half * DPH;

    // x half2-pairs of both batches at this block's 32 d-pairs
    __shared__ uint2 s_x[DPH];
    if (u < DPH) {
        const float2* in2 = (const float2*)inputs;
        float2 xa = in2[(b0 * IDIM + 2 * dbase) / 2 + u];
        float2 xb = in2[((b0 + 1) * IDIM + 2 * dbase) / 2 + u];
        uint2 p;
        p.x = h2u(__halves2half2(__float2half_rn(xa.x), __float2half_rn(xa.y)));
        p.y = h2u(__halves2half2(__float2half_rn(xb.x), __float2half_rn(xb.y)));
        s_x[u] = p;
    }
    __syncthreads();

    u64 acc0 = 0, st0 = 0;
    u64 acc1 = 0, st1 = 0;

    const uint4* __restrict__ w = &g_w[dbase * UNITS + u];

    #pragma unroll
    for (int d2 = 0; d2 < DPH; ++d2) {
        uint4 wv = __ldg(&w[d2 * UNITS]);   // LDG.128: sH2, cH2, AH0, AH1
        uint2 xp = s_x[d2];                 // LDS.64 broadcast

        u64 a2 = pack2(__uint_as_float(wv.z), __uint_as_float(wv.w));
        __half2 sh2 = u2h(wv.x), ch2 = u2h(wv.y);

        {   // batch 0
            __half2 t = u2h(tanh2u(h2u(__hfma2(sh2, u2h(xp.x), ch2))));
            u64 tp = pack2(__low2float(t), __high2float(t));
            acc0 = fma2(tp, a2, acc0);
            st0  = add2(tp, st0);
        }
        {   // batch 1
            __half2 t = u2h(tanh2u(h2u(__hfma2(sh2, u2h(xp.y), ch2))));
            u64 tp = pack2(__low2float(t), __high2float(t));
            acc1 = fma2(tp, a2, acc1);
            st1  = add2(tp, st1);
        }
    }

    {
        float2 a = unpack2(acc0), s = unpack2(st0);
        g_part[half][b0 * UNITS + u] = make_float2(a.x + a.y, s.x + s.y);
    }
    {
        float2 a = unpack2(acc1), s = unpack2(st1);
        g_part[half][(b0 + 1) * UNITS + u] = make_float2(a.x + a.y, s.x + s.y);
    }
}

// Phase 2: one thread per (batch, unit).
__global__ __launch_bounds__(256)
void ode_combine_kernel(const float* __restrict__ state,
                        float* __restrict__ out) {
    const int i = blockIdx.x * 256 + threadIdx.x;   // i = b*UNITS + u
    const int u = i & (UNITS - 1);

    float2 p0 = g_part[0][i];
    float2 p1 = g_part[1][i];

    float fA = g_baseA[u] + p0.x + p1.x;
    float fs = (float)(IDIM / 2) + 0.5f * (p0.y + p1.y);
    float am = 1.0f - DT_U * (OMEGA + fs);
    float c  = DT_U * fA;
    float x  = state[i];
    #pragma unroll
    for (int k = 0; k < 6; ++k) x = fmaf(x, am, c);
    out[i] = x;
}

extern "C" void kernel_launch(void* const* d_in, const int* in_sizes, int n_in,
                              void* d_out, int out_size) {
    const float* inputs = (const float*)d_in[0];
    const float* state  = (const float*)d_in[1];
    const float* A      = (const float*)d_in[2];
    const float* sigma  = (const float*)d_in[3];
    const float* mu     = (const float*)d_in[4];
    float* out = (float*)d_out;

    ode_prep_kernel<<<UNITS, DP>>>(A, sigma, mu);
    ode_partial_kernel<<<(BATCH / BB) * DSPLIT, UNITS>>>(inputs);
    ode_combine_kernel<<<(BATCH * UNITS) / 256, 256>>>(state, out);
}

// round 8
// speedup vs baseline: 1.1552x; 1.1552x over previous
#include <cuda_runtime.h>
#include <cuda_fp16.h>

// ODECell: f = sigmoid(sigma*(in-mu)) = 0.5 + 0.5*tanh(0.5*sigma*(in-mu))
//   t = tanh(sH*x + cH);  fA = baseA[u] + sum_d t*AH;  fs = 64 + 0.5*sum_d t
//   x <- 6 Euler steps of x*(1 - dt*(omega+fs)) + dt*fA
//
// R8: grouped f16x2 accumulation (HFMA2/HADD2, flush to f32x2 every 16 dims)
// removes F2F from the inner loop; AH stored f16x2 (24B per 4 dims).
// BB=2, grid 1024, launch_bounds(128,8).

#define UNITS 128
#define IDIM  128
#define DP    (IDIM / 2)     // 64 d-pairs
#define NQ    (DP / 2)       // 32 d-quads (4 dims each)
#define GQ    4              // quads per flush group (16 dims)
#define NG    (NQ / GQ)      // 8 groups
#define BATCH 2048
#define BB    2
#define OMEGA 0.1f
#define DT_U  (0.1f / 6.0f)

typedef unsigned int       u32;
typedef unsigned long long u64;

// Weight streams, transposed [quad][u]:
//   g_wsc: {sH2_a, cH2_a, sH2_b, cH2_b}  (uint4, 16B per 4 dims)
//   g_wa : {AH2_a, AH2_b}                (uint2,  8B per 4 dims)
__device__ uint4 g_wsc[NQ * UNITS];
__device__ uint2 g_wa [NQ * UNITS];
__device__ float g_baseA[UNITS];

__device__ __forceinline__ u32 h2u(__half2 h) {
    u32 r; __builtin_memcpy(&r, &h, 4); return r;
}
__device__ __forceinline__ __half2 u2h(u32 u) {
    __half2 r; __builtin_memcpy(&r, &u, 4); return r;
}
__device__ __forceinline__ u32 tanh2u(u32 z) {
    u32 y; asm("tanh.approx.f16x2 %0, %1;" : "=r"(y) : "r"(z)); return y;
}
__device__ __forceinline__ u32 hfma2u(u32 a, u32 b, u32 c) {
    return h2u(__hfma2(u2h(a), u2h(b), u2h(c)));
}
__device__ __forceinline__ u32 hadd2u(u32 a, u32 b) {
    return h2u(__hadd2(u2h(a), u2h(b)));
}
__device__ __forceinline__ u64 pack2(float lo, float hi) {
    u64 p;
    asm("mov.b64 %0, {%1, %2};" : "=l"(p)
        : "r"(__float_as_uint(lo)), "r"(__float_as_uint(hi)));
    return p;
}
__device__ __forceinline__ u64 add2(u64 a, u64 b) {
    u64 d; asm("add.rn.f32x2 %0, %1, %2;" : "=l"(d) : "l"(a), "l"(b));
    return d;
}
__device__ __forceinline__ float2 unpack2(u64 p) {
    u32 lo, hi;
    asm("mov.b64 {%0, %1}, %2;" : "=r"(lo), "=r"(hi) : "l"(p));
    return make_float2(__uint_as_float(lo), __uint_as_float(hi));
}
// f16x2 -> packed f32x2
__device__ __forceinline__ u64 cvt2(u32 h) {
    __half2 hh = u2h(h);
    return pack2(__low2float(hh), __high2float(hh));
}

// One block per unit u, 64 threads (one per d-pair): pack weights + reduce baseA.
__global__ void ode_prep_kernel(const float* __restrict__ A,
                                const float* __restrict__ sigma,
                                const float* __restrict__ mu) {
    const int u   = blockIdx.x;
    const int d2  = threadIdx.x;          // 0..63
    const int i   = u * IDIM + 2 * d2;
    const int q   = d2 >> 1;              // quad index
    const int sub = d2 & 1;               // a/b within quad

    float s0 = sigma[i],  s1 = sigma[i + 1];
    float m0 = mu[i],     m1 = mu[i + 1];
    float a0 = 0.5f * A[i], a1 = 0.5f * A[i + 1];

    u32 sh2 = h2u(__halves2half2(__float2half_rn(0.5f * s0), __float2half_rn(0.5f * s1)));
    u32 ch2 = h2u(__halves2half2(__float2half_rn(-0.5f * s0 * m0),
                                 __float2half_rn(-0.5f * s1 * m1)));
    u32 ah2 = h2u(__halves2half2(__float2half_rn(a0), __float2half_rn(a1)));

    // wsc uint4 slot: [sh_a, ch_a, sh_b, ch_b]; thread writes its half (8B aligned)
    u32* wsc = (u32*)&g_wsc[q * UNITS + u];
    wsc[sub * 2 + 0] = sh2;
    wsc[sub * 2 + 1] = ch2;
    u32* wa = (u32*)&g_wa[q * UNITS + u];
    wa[sub] = ah2;

    __shared__ float red[2];
    float v = a0 + a1;
    #pragma unroll
    for (int off = 16; off > 0; off >>= 1)
        v += __shfl_down_sync(0xffffffffu, v, off);
    if ((d2 & 31) == 0) red[d2 >> 5] = v;
    __syncthreads();
    if (d2 == 0) g_baseA[u] = red[0] + red[1];
}

__global__ __launch_bounds__(UNITS, 8)
void ode_main_kernel(const float* __restrict__ inputs,
                     const float* __restrict__ state,
                     float* __restrict__ out) {
    const int u  = threadIdx.x;
    const int b0 = blockIdx.x * BB;

    // s_x[q] = {x2_b0 dims(4q,4q+1), x2_b1 same, x2_b0 dims(4q+2,4q+3), x2_b1 same}
    __shared__ u32 s_x[DP * 2];
    if (u < DP) {
        const float2* in2 = (const float2*)inputs;
        float2 xa = in2[(b0 * IDIM) / 2 + u];
        float2 xb = in2[((b0 + 1) * IDIM) / 2 + u];
        s_x[2 * u + 0] = h2u(__halves2half2(__float2half_rn(xa.x), __float2half_rn(xa.y)));
        s_x[2 * u + 1] = h2u(__halves2half2(__float2half_rn(xb.x), __float2half_rn(xb.y)));
    }
    __syncthreads();
    const uint4* s_x4 = (const uint4*)s_x;   // [q] -> {xb0_a, xb1_a, xb0_b, xb1_b}

    u64 acc0 = 0, st0 = 0;   // packed f32x2 totals per batch
    u64 acc1 = 0, st1 = 0;

    const uint4* __restrict__ wsc = &g_wsc[u];
    const uint2* __restrict__ wa  = &g_wa[u];

    #pragma unroll
    for (int g = 0; g < NG; ++g) {
        u32 accg0 = 0, stg0 = 0;   // f16x2 group accumulators (+0,+0)
        u32 accg1 = 0, stg1 = 0;

        #pragma unroll
        for (int j = 0; j < GQ; ++j) {
            const int q = g * GQ + j;
            uint4 wv = __ldg(&wsc[q * UNITS]);   // LDG.128
            uint2 av = __ldg(&wa [q * UNITS]);   // LDG.64
            uint4 xp = s_x4[q];                  // LDS.128 broadcast

            // subpair a (dims 4q, 4q+1)
            u32 ta0 = tanh2u(hfma2u(wv.x, xp.x, wv.y));
            u32 ta1 = tanh2u(hfma2u(wv.x, xp.y, wv.y));
            accg0 = hfma2u(ta0, av.x, accg0);  stg0 = hadd2u(stg0, ta0);
            accg1 = hfma2u(ta1, av.x, accg1);  stg1 = hadd2u(stg1, ta1);

            // subpair b (dims 4q+2, 4q+3)
            u32 tb0 = tanh2u(hfma2u(wv.z, xp.z, wv.w));
            u32 tb1 = tanh2u(hfma2u(wv.z, xp.w, wv.w));
            accg0 = hfma2u(tb0, av.y, accg0);  stg0 = hadd2u(stg0, tb0);
            accg1 = hfma2u(tb1, av.y, accg1);  stg1 = hadd2u(stg1, tb1);
        }

        acc0 = add2(acc0, cvt2(accg0));  st0 = add2(st0, cvt2(stg0));
        acc1 = add2(acc1, cvt2(accg1));  st1 = add2(st1, cvt2(stg1));
    }

    const float baseA = g_baseA[u];

    {
        float2 a = unpack2(acc0), s = unpack2(st0);
        float fA = baseA + a.x + a.y;
        float fs = (float)(IDIM / 2) + 0.5f * (s.x + s.y);
        float am = 1.0f - DT_U * (OMEGA + fs);
        float c  = DT_U * fA;
        float x  = state[b0 * UNITS + u];
        #pragma unroll
        for (int k = 0; k < 6; ++k) x = fmaf(x, am, c);
        out[b0 * UNITS + u] = x;
    }
    {
        float2 a = unpack2(acc1), s = unpack2(st1);
        float fA = baseA + a.x + a.y;
        float fs = (float)(IDIM / 2) + 0.5f * (s.x + s.y);
        float am = 1.0f - DT_U * (OMEGA + fs);
        float c  = DT_U * fA;
        float x  = state[(b0 + 1) * UNITS + u];
        #pragma unroll
        for (int k = 0; k < 6; ++k) x = fmaf(x, am, c);
        out[(b0 + 1) * UNITS + u] = x;
    }
}

extern "C" void kernel_launch(void* const* d_in, const int* in_sizes, int n_in,
                              void* d_out, int out_size) {
    const float* inputs = (const float*)d_in[0];
    const float* state  = (const float*)d_in[1];
    const float* A      = (const float*)d_in[2];
    const float* sigma  = (const float*)d_in[3];
    const float* mu     = (const float*)d_in[4];
    float* out = (float*)d_out;

    ode_prep_kernel<<<UNITS, DP>>>(A, sigma, mu);
    ode_main_kernel<<<BATCH / BB, UNITS>>>(inputs, state, out);
}